// round 10
// baseline (speedup 1.0000x reference)
#include <cuda_runtime.h>
#include <cuda_fp16.h>
#include <math.h>

typedef unsigned int u32;

// ---------------- static device scratch (allocation-free rule) ----------------
__device__ __half g_xh[48*48*320];          // L1 input NHWC fp16
__device__ __half g_h0[96*96*192];          // L1 out / L2 in
__device__ __half g_h1[192*192*192];        // L2 out / L3 in
__device__ __half g_h2[384*384*192];        // L3 out / L4 in
__device__ __half g_wt1[25*192*320];        // [tap][co][ci]
__device__ __half g_wt2[25*192*192];
__device__ __half g_wt3[25*192*192];
__device__ __half g_wt4[9*16*192];          // [tap][n=(parity*4+co)][ci]
__device__ float g_b1q[192];
__device__ float g_b2q[192];
__device__ float g_b3q[192];
__device__ float g_b4q[3];
__device__ float g_params[24];

// ---------------- PTX wrappers ----------------
#define CPASYNC(dst, src, sz) \
    asm volatile("cp.async.cg.shared.global [%0], [%1], 16, %2;" :: "r"(dst), "l"(src), "r"(sz))
#define CPCOMMIT() asm volatile("cp.async.commit_group;")
#define CPWAIT(n)  asm volatile("cp.async.wait_group %0;" :: "n"(n))
#define LDSM4(r0,r1,r2,r3,addr) \
    asm volatile("ldmatrix.sync.aligned.m8n8.x4.shared.b16 {%0,%1,%2,%3}, [%4];" \
        : "=r"(r0),"=r"(r1),"=r"(r2),"=r"(r3) : "r"(addr))
#define MMA16816(c0,c1,c2,c3,a0,a1,a2,a3,b0,b1) \
    asm volatile("mma.sync.aligned.m16n8k16.row.col.f32.f16.f16.f32 " \
        "{%0,%1,%2,%3}, {%4,%5,%6,%7}, {%8,%9}, {%0,%1,%2,%3};" \
        : "+f"(c0),"+f"(c1),"+f"(c2),"+f"(c3) \
        : "r"(a0),"r"(a1),"r"(a2),"r"(a3),"r"(b0),"r"(b1))

// ---------------- small prep kernels ----------------
__global__ void quant_biases(const float* __restrict__ b1, const float* __restrict__ b2,
                             const float* __restrict__ b3, const float* __restrict__ b4) {
    int i = threadIdx.x;
    if (i < 192) {
        g_b1q[i] = rintf(b1[i]);
        g_b2q[i] = rintf(b2[i]);
        g_b3q[i] = rintf(b3[i]);
    }
    if (i < 3) g_b4q[i] = rintf(b4[i]);
}

__global__ void prep_kernel(const float* __restrict__ relus,
                            const int* __restrict__ dvds,
                            const int* __restrict__ bitsp) {
    if (threadIdx.x == 0 && blockIdx.x == 0) {
        float B = bitsp ? (float)(*bitsp) : 8.0f;
        float maxv = exp2f(B) - 1.0f;
        const int sks[3] = {3, 4, 3};
        for (int i = 0; i < 3; i++) {
            float dv = (float)dvds[i];
            g_params[i*6+0] = exp2f(dv - 10.0f);
            g_params[i*6+1] = exp2f(9.0f - dv);
            g_params[i*6+2] = rintf((maxv / relus[i]) * 33554432.0f);
            float sk = (float)sks[i];
            g_params[i*6+3] = floorf((relus[i] + exp2f(sk - 1.0f)) * exp2f(-sk));
            g_params[i*6+4] = exp2f(24.0f - sk);
            g_params[i*6+5] = exp2f(sk - 25.0f);
        }
        float dv3 = (float)dvds[3];
        g_params[18] = exp2f(dv3 - 9.0f);
        g_params[19] = exp2f(8.0f - dv3);
    }
}

// NCHW f32 -> NHWC fp16 (values are small ints: exact)
__global__ void nchw2nhwc(const float* __restrict__ src, __half* __restrict__ dst,
                          int C, int HW) {
    int idx = blockIdx.x * blockDim.x + threadIdx.x;
    if (idx >= C * HW) return;
    int s = idx / C, c = idx % C;
    dst[idx] = __float2half_rn(src[c * HW + s]);
}

// All three big weights in one launch: w [CIN][192][5][5] -> wt [tap][co][ci].
__global__ void prep_w3x(const float* __restrict__ w1, const float* __restrict__ w2,
                         const float* __restrict__ w3,
                         __half* __restrict__ wt1, __half* __restrict__ wt2,
                         __half* __restrict__ wt3) {
    __shared__ float tile[320 * 25];
    const int which = blockIdx.y;
    const float* w = which == 0 ? w1 : (which == 1 ? w2 : w3);
    __half* wt     = which == 0 ? wt1 : (which == 1 ? wt2 : wt3);
    const int CIN  = which == 0 ? 320 : 192;
    const int COUT = 192;
    const int co = blockIdx.x;
    const int tid = threadIdx.x;
    for (int i = tid; i < CIN * 25; i += 256) {
        int ci = i / 25, t = i % 25;
        tile[i] = w[((size_t)ci * COUT + co) * 25 + t];
    }
    __syncthreads();
    const int nc8 = CIN >> 3;
    for (int i = tid; i < 25 * nc8; i += 256) {
        int t = i / nc8, c8 = i % nc8;
        __half h[8];
        #pragma unroll
        for (int j = 0; j < 8; j++)
            h[j] = __float2half_rn(rintf(tile[(c8 * 8 + j) * 25 + t]));
        *(uint4*)(wt + ((size_t)t * COUT + co) * CIN + c8 * 8) = *(uint4*)h;
    }
}

// L4: w [192][3][5][5] -> wt4 [9][16][192], n=(py*2+px)*4+co, zeros for invalid/pad
__global__ void prep_w4(const float* __restrict__ w, __half* __restrict__ wt) {
    int idx = blockIdx.x * blockDim.x + threadIdx.x;
    if (idx >= 9 * 16 * 192) return;
    int t = idx / (16 * 192);
    int r = idx % (16 * 192);
    int n = r / 192;
    int ci = r % 192;
    int dy = t / 3 - 1, dx = t % 3 - 1;
    int p = n >> 2, co = n & 3;
    int py = p >> 1, px = p & 1;
    float v = 0.f;
    if (co < 3 && (py == 0 || dy >= 0) && (px == 0 || dx >= 0)) {
        int ky = py + 2 - 2 * dy, kx = px + 2 - 2 * dx;
        v = rintf(w[((size_t)ci * 3 + co) * 25 + ky * 5 + kx]);
    }
    wt[idx] = __float2half_rn(v);
}

// ---------------- R7 tensor-core transposed conv (per-z CTA) ----------------
template<int NTILE, int WM, int WN, int YR, bool LAST>
__global__ void __launch_bounds__(256, 2) conv_mma(
    const __half* __restrict__ inA, void* __restrict__ outp,
    const __half* __restrict__ Wt, const float* __restrict__ bq,
    const float* __restrict__ mul,
    int CIN, int COUT, int H, int W, int stage)
{
    constexpr int MI = YR / WM;
    constexpr int NI = NTILE / (8 * WN);
    constexpr int NPAIR = NI / 2;
    constexpr int NSITES = (YR + 2) * 18;
    constexpr int ASTG = NSITES * 48;
    constexpr int BSTG = NTILE * 48;
    __shared__ __align__(16) char smem[2 * ASTG + 4 * BSTG];

    const int tid = threadIdx.x;
    const int lane = tid & 31, wid = tid >> 5;
    const int warp_m = wid % WM, warp_n = wid / WM;
    const int x0 = blockIdx.x * 16, y0 = blockIdx.y * YR;
    int py, px, co0;
    if (LAST) { py = 0; px = 0; co0 = 0; }
    else { py = blockIdx.z & 1; px = (blockIdx.z >> 1) & 1; co0 = (blockIdx.z >> 2) * 64; }

    int ntaps, tAoff[9], tBrow[9];
    if (LAST) {
        ntaps = 9;
        #pragma unroll
        for (int t = 0; t < 9; t++) { tAoff[t] = ((t / 3) * 18 + (t % 3)) * 48; tBrow[t] = t * 16; }
    } else {
        ntaps = 0;
        for (int dy = (py ? 0 : -1); dy <= 1; dy++)
            for (int dx = (px ? 0 : -1); dx <= 1; dx++) {
                tAoff[ntaps] = ((dy + 1) * 18 + (dx + 1)) * 48;
                tBrow[ntaps] = ((py + 2 - 2 * dy) * 5 + (px + 2 - 2 * dx)) * COUT + co0;
                ntaps++;
            }
    }
    const int nchunks = CIN >> 4;
    const int niter = nchunks * ntaps;

    const u32 smem_u = (u32)__cvta_generic_to_shared(smem);
    const u32 Abase = smem_u;
    const u32 Bbase = smem_u + 2 * ASTG;

    auto loadA = [&](int chunk, int slot) {
        const int ci0 = chunk << 4;
        #pragma unroll
        for (int k = 0; k < (NSITES * 2 + 255) / 256; k++) {
            int idx = tid + k * 256;
            if (idx < NSITES * 2) {
                int site = idx >> 1, seg = idx & 1;
                int r = site / 18, c = site % 18;
                int gy = y0 - 1 + r, gx = x0 - 1 + c;
                bool ok = (unsigned)gy < (unsigned)H && (unsigned)gx < (unsigned)W;
                const __half* src = ok ? (inA + ((size_t)(gy * W + gx) * CIN + ci0 + seg * 8)) : inA;
                u32 dst = Abase + slot * ASTG + site * 48 + seg * 16;
                CPASYNC(dst, src, ok ? 16 : 0);
            }
        }
    };
    auto loadB = [&](int tap, int chunk, int slot) {
        const int ci0 = chunk << 4;
        if (tid < NTILE * 2) {
            int n = tid >> 1, seg = tid & 1;
            const __half* src = Wt + (size_t)(tBrow[tap] + n) * CIN + ci0 + seg * 8;
            u32 dst = Bbase + slot * BSTG + n * 48 + seg * 16;
            CPASYNC(dst, src, 16);
        }
    };

    loadA(0, 0); loadB(0, 0, 0); CPCOMMIT();
    loadB(1, 0, 1); CPCOMMIT();
    loadB(2, 0, 2); CPCOMMIT();

    float acc[MI][NI][4];
    #pragma unroll
    for (int mi = 0; mi < MI; mi++)
        #pragma unroll
        for (int ni = 0; ni < NI; ni++)
            #pragma unroll
            for (int k = 0; k < 4; k++) acc[mi][ni][k] = 0.f;

    const int la = lane & 7, ms = lane >> 3;
    const u32 aoff_lane = (u32)((la + ((ms & 1) << 3)) * 48 + ((ms >> 1) << 4));
    const u32 boff_lane = (u32)((la + ((lane >> 4) << 3)) * 48 + (((lane >> 3) & 1) << 4));

    int cur_tap = 0, cur_chunk = 0;
    int pf_tap = 3, pf_chunk = 0;

    for (int i = 0; i < niter; i++) {
        CPWAIT(2);
        __syncthreads();
        if (i + 3 < niter) loadB(pf_tap, pf_chunk, (i + 3) & 3);
        if (cur_tap == 0 && cur_chunk + 1 < nchunks) loadA(cur_chunk + 1, (cur_chunk + 1) & 1);
        CPCOMMIT();

        const u32 Astage = Abase + (cur_chunk & 1) * ASTG + tAoff[cur_tap] + aoff_lane;
        const u32 Bstage = Bbase + (i & 3) * BSTG + warp_n * (NI * 8 * 48) + boff_lane;

        u32 a[MI][4], b[NPAIR][4];
        #pragma unroll
        for (int mi = 0; mi < MI; mi++) {
            int ylocal = warp_m * MI + mi;
            LDSM4(a[mi][0], a[mi][1], a[mi][2], a[mi][3], Astage + ylocal * (18 * 48));
        }
        #pragma unroll
        for (int p2 = 0; p2 < NPAIR; p2++)
            LDSM4(b[p2][0], b[p2][1], b[p2][2], b[p2][3], Bstage + p2 * (16 * 48));

        #pragma unroll
        for (int mi = 0; mi < MI; mi++)
            #pragma unroll
            for (int ni = 0; ni < NI; ni++)
                MMA16816(acc[mi][ni][0], acc[mi][ni][1], acc[mi][ni][2], acc[mi][ni][3],
                         a[mi][0], a[mi][1], a[mi][2], a[mi][3],
                         b[ni >> 1][(ni & 1) * 2], b[ni >> 1][(ni & 1) * 2 + 1]);

        if (++cur_tap == ntaps) { cur_tap = 0; cur_chunk++; }
        if (++pf_tap == ntaps) { pf_tap = 0; pf_chunk++; }
    }
    CPWAIT(0);

    float addA, invA, clpv = 0.f, sclv = 0.f, addB = 0.f, invB = 0.f;
    if (!LAST) {
        addA = g_params[stage*6+0]; invA = g_params[stage*6+1];
        clpv = g_params[stage*6+2]; sclv = g_params[stage*6+3];
        addB = g_params[stage*6+4]; invB = g_params[stage*6+5];
    } else {
        addA = g_params[18]; invA = g_params[19];
    }
    const int W2 = 2 * W;

    if (!LAST) {
        __half* out = (__half*)outp;
        #pragma unroll
        for (int mi = 0; mi < MI; mi++) {
            int ylocal = warp_m * MI + mi;
            int oy = 2 * (y0 + ylocal) + py;
            #pragma unroll
            for (int ni = 0; ni < NI; ni++) {
                int co = co0 + warp_n * (NI * 8) + ni * 8 + (lane & 3) * 2;
                float b0f = bq[co], b1f = bq[co + 1];
                float m0f = mul[co], m1f = mul[co + 1];
                #pragma unroll
                for (int h = 0; h < 2; h++) {
                    int xl = (lane >> 2) + h * 8;
                    int ox = 2 * (x0 + xl) + px;
                    float v0 = acc[mi][ni][h * 2 + 0];
                    float v1 = acc[mi][ni][h * 2 + 1];
                    v0 = floorf(((v0 + b0f) * m0f + addA) * invA);
                    v0 = fminf(fmaxf(v0, 0.f), clpv);
                    v0 = floorf((v0 * sclv + addB) * invB);
                    v1 = floorf(((v1 + b1f) * m1f + addA) * invA);
                    v1 = fminf(fmaxf(v1, 0.f), clpv);
                    v1 = floorf((v1 * sclv + addB) * invB);
                    __half2 hv = __floats2half2_rn(v0, v1);
                    *(__half2*)(out + ((size_t)oy * W2 + ox) * COUT + co) = hv;
                }
            }
        }
    } else {
        float* out = (float*)outp;
        const int PLANE = W2 * 2 * H;
        #pragma unroll
        for (int mi = 0; mi < MI; mi++) {
            int ylocal = warp_m * MI + mi;
            #pragma unroll
            for (int ni = 0; ni < NI; ni++) {
                int nbase = ni * 8 + (lane & 3) * 2;
                #pragma unroll
                for (int h = 0; h < 2; h++) {
                    int xl = (lane >> 2) + h * 8;
                    #pragma unroll
                    for (int j = 0; j < 2; j++) {
                        int n = nbase + j;
                        int p = n >> 2, c = n & 3;
                        if (c < 3) {
                            int pyy = p >> 1, pxx = p & 1;
                            int oy = 2 * (y0 + ylocal) + pyy;
                            int ox = 2 * (x0 + xl) + pxx;
                            float v = acc[mi][ni][h * 2 + j];
                            v = (v + bq[c]) * mul[c];
                            v = floorf((v + addA) * invA);
                            out[(size_t)c * PLANE + (size_t)oy * W2 + ox] = v / 255.0f;
                        }
                    }
                }
            }
        }
    }
}

// ---------------- A-resident conv for L3 (CIN=COUT=192) ----------------
// CTA = 16x16-site tile. Stage ALL 192 ci of A once (site pitch 400B,
// conflict-free ldmatrix). Loop 12 rounds (4 parity x 3 co64), streaming only B
// (32B rows, XOR-swizzled) through a 4-slot cp.async ring with +3 prefetch.
__global__ void __launch_bounds__(256) conv_res(
    const __half* __restrict__ inA, __half* __restrict__ out,
    const __half* __restrict__ Wt, const float* __restrict__ bq,
    const float* __restrict__ mul, int H, int W)
{
    constexpr int CIN = 192, COUT = 192;
    constexpr int APITCH = 400;
    constexpr int ASIZE = 324 * APITCH;     // 129600
    constexpr int BSTG = 64 * 32;           // 2048
    constexpr int TOT = 900;                // 3 cog * 12 chunks * 25 taps
    extern __shared__ __align__(16) char smem[];

    const int tid = threadIdx.x;
    const int lane = tid & 31, wid = tid >> 5;      // wid = warp_m (WM=8)
    const int x0 = blockIdx.x * 16, y0 = blockIdx.y * 16;

    const u32 Abase = (u32)__cvta_generic_to_shared(smem);
    const u32 Bbase = Abase + ASIZE;
    int* sTB = (int*)(smem + ASIZE + 4 * BSTG);     // [4][9] B row bases
    int* sTA = sTB + 36;                            // [4][9] A byte offsets

    // ---- stage A: 324 sites x 24 16B-segs (all 192 ci)
    for (int idx = tid; idx < 324 * 24; idx += 256) {
        int site = idx / 24, seg = idx % 24;
        int r = site / 18, c = site % 18;
        int gy = y0 - 1 + r, gx = x0 - 1 + c;
        bool ok = (unsigned)gy < (unsigned)H && (unsigned)gx < (unsigned)W;
        const __half* src = ok ? (inA + ((size_t)(gy * W + gx) * CIN + seg * 8)) : inA;
        CPASYNC(Abase + site * APITCH + seg * 16, src, ok ? 16 : 0);
    }
    CPCOMMIT();                                     // group 0 = A

    // ---- tap tables into smem
    if (tid < 36) {
        int p = tid / 9, t = tid % 9;
        int py = p >> 1, px = p & 1;
        int ndx = px ? 2 : 3;
        int nt = (py ? 2 : 3) * ndx;
        if (t < nt) {
            int dy = (py ? 0 : -1) + t / ndx;
            int dx = (px ? 0 : -1) + t % ndx;
            sTA[p * 9 + t] = ((dy + 1) * 18 + (dx + 1)) * APITCH;
            sTB[p * 9 + t] = ((py + 2 - 2 * dy) * 5 + (px + 2 - 2 * dx)) * COUT;
        }
    }
    __syncthreads();

    auto loadB = [&](int pp, int pg, int ptap, int pchunk, int slot) {
        if (tid < 128) {
            int n = tid >> 1, seg = tid & 1;
            int row = sTB[pp * 9 + ptap] + pg * 64 + n;
            const __half* src = Wt + (size_t)row * CIN + pchunk * 16 + seg * 8;
            u32 dst = Bbase + slot * BSTG + n * 32 + (u32)((seg ^ ((n >> 2) & 1)) << 4);
            CPASYNC(dst, src, 16);
        }
    };

    // prefetch odometer (tap fastest, then chunk, then cog, then parity)
    int pp = 0, pg = 0, pchunk = 0, ptap = 0;
    auto pfadv = [&]() {
        int nt = (0x4669 >> (pp << 2)) & 15;        // {9,6,6,4}
        if (++ptap == nt) { ptap = 0;
            if (++pchunk == 12) { pchunk = 0;
                if (++pg == 3) { pg = 0; ++pp; } } }
    };
    loadB(pp, pg, ptap, pchunk, 0); pfadv(); CPCOMMIT();
    loadB(pp, pg, ptap, pchunk, 1); pfadv(); CPCOMMIT();
    loadB(pp, pg, ptap, pchunk, 2); pfadv(); CPCOMMIT();
    int rem = TOT - 3;

    const int la = lane & 7, ms = lane >> 3;
    const u32 aoff_lane = (u32)((la + ((ms & 1) << 3)) * APITCH + ((ms >> 1) << 4));
    const int rb = la + ((lane >> 4) << 3);
    const int sb = (lane >> 3) & 1;
    const u32 boff_lane = (u32)(rb * 32 + ((sb ^ ((rb >> 2) & 1)) << 4));

    const float addA = g_params[12], invA = g_params[13];
    const float clpv = g_params[14], sclv = g_params[15];
    const float addB = g_params[16], invB = g_params[17];
    const int W2 = 2 * W;

    int gi = 0;
    for (int p = 0; p < 4; p++) {
        const int py = p >> 1, px = p & 1;
        const int nt = (0x4669 >> (p << 2)) & 15;
        for (int g = 0; g < 3; g++) {
            float acc[2][8][4];
            #pragma unroll
            for (int mi = 0; mi < 2; mi++)
                #pragma unroll
                for (int ni = 0; ni < 8; ni++)
                    #pragma unroll
                    for (int k = 0; k < 4; k++) acc[mi][ni][k] = 0.f;

            for (int chunk = 0; chunk < 12; chunk++) {
                for (int t = 0; t < nt; t++) {
                    CPWAIT(2);
                    __syncthreads();
                    if (rem > 0) { loadB(pp, pg, ptap, pchunk, (gi + 3) & 3); pfadv(); rem--; }
                    CPCOMMIT();

                    const u32 Astage = Abase + sTA[p * 9 + t] + chunk * 32 + aoff_lane;
                    const u32 Bstage = Bbase + (gi & 3) * BSTG + boff_lane;

                    u32 a[2][4], b[4][4];
                    #pragma unroll
                    for (int mi = 0; mi < 2; mi++) {
                        int yl = wid * 2 + mi;
                        LDSM4(a[mi][0], a[mi][1], a[mi][2], a[mi][3],
                              Astage + yl * (18 * APITCH));
                    }
                    #pragma unroll
                    for (int p2 = 0; p2 < 4; p2++)
                        LDSM4(b[p2][0], b[p2][1], b[p2][2], b[p2][3], Bstage + p2 * 512);

                    #pragma unroll
                    for (int mi = 0; mi < 2; mi++)
                        #pragma unroll
                        for (int ni = 0; ni < 8; ni++)
                            MMA16816(acc[mi][ni][0], acc[mi][ni][1], acc[mi][ni][2], acc[mi][ni][3],
                                     a[mi][0], a[mi][1], a[mi][2], a[mi][3],
                                     b[ni >> 1][(ni & 1) * 2], b[ni >> 1][(ni & 1) * 2 + 1]);
                    gi++;
                }
            }

            // epilogue for round (p, g)
            #pragma unroll
            for (int mi = 0; mi < 2; mi++) {
                int yl = wid * 2 + mi;
                int oy = 2 * (y0 + yl) + py;
                #pragma unroll
                for (int ni = 0; ni < 8; ni++) {
                    int co = g * 64 + ni * 8 + (lane & 3) * 2;
                    float b0f = bq[co], b1f = bq[co + 1];
                    float m0f = mul[co], m1f = mul[co + 1];
                    #pragma unroll
                    for (int h = 0; h < 2; h++) {
                        int xl = (lane >> 2) + h * 8;
                        int ox = 2 * (x0 + xl) + px;
                        float v0 = acc[mi][ni][h * 2 + 0];
                        float v1 = acc[mi][ni][h * 2 + 1];
                        v0 = floorf(((v0 + b0f) * m0f + addA) * invA);
                        v0 = fminf(fmaxf(v0, 0.f), clpv);
                        v0 = floorf((v0 * sclv + addB) * invB);
                        v1 = floorf(((v1 + b1f) * m1f + addA) * invA);
                        v1 = fminf(fmaxf(v1, 0.f), clpv);
                        v1 = floorf((v1 * sclv + addB) * invB);
                        __half2 hv = __floats2half2_rn(v0, v1);
                        *(__half2*)(out + ((size_t)oy * W2 + ox) * COUT + co) = hv;
                    }
                }
            }
        }
    }
    CPWAIT(0);
}

// ---------------- host launcher (graph-capturable: kernel launches only) -------
extern "C" void kernel_launch(void* const* d_in, const int* in_sizes, int n_in,
                              void* d_out, int out_size)
{
    const float* x     = (const float*)d_in[0];
    const float* w1    = (const float*)d_in[1];
    const float* b1    = (const float*)d_in[2];
    const float* w2    = (const float*)d_in[3];
    const float* b2    = (const float*)d_in[4];
    const float* w3    = (const float*)d_in[5];
    const float* b3    = (const float*)d_in[6];
    const float* w4    = (const float*)d_in[7];
    const float* b4    = (const float*)d_in[8];
    const float* m0    = (const float*)d_in[9];
    const float* m1    = (const float*)d_in[10];
    const float* m2    = (const float*)d_in[11];
    const float* m3    = (const float*)d_in[12];
    const float* relus = (const float*)d_in[13];
    const int*   dvds  = (const int*)d_in[14];
    const int*   bitsp = (n_in > 15) ? (const int*)d_in[15] : nullptr;

    __half *xh, *h0, *h1, *h2, *wt1, *wt2, *wt3, *wt4;
    float *b1q, *b2q, *b3q, *b4q;
    cudaGetSymbolAddress((void**)&xh,  g_xh);
    cudaGetSymbolAddress((void**)&h0,  g_h0);
    cudaGetSymbolAddress((void**)&h1,  g_h1);
    cudaGetSymbolAddress((void**)&h2,  g_h2);
    cudaGetSymbolAddress((void**)&wt1, g_wt1);
    cudaGetSymbolAddress((void**)&wt2, g_wt2);
    cudaGetSymbolAddress((void**)&wt3, g_wt3);
    cudaGetSymbolAddress((void**)&wt4, g_wt4);
    cudaGetSymbolAddress((void**)&b1q, g_b1q);
    cudaGetSymbolAddress((void**)&b2q, g_b2q);
    cudaGetSymbolAddress((void**)&b3q, g_b3q);
    cudaGetSymbolAddress((void**)&b4q, g_b4q);

    nchw2nhwc<<<(48*48*320 + 255)/256, 256>>>(x, xh, 320, 48*48);
    prep_w3x<<<dim3(192, 3), 256>>>(w1, w2, w3, wt1, wt2, wt3);
    prep_w4<<<(9*16*192 + 255)/256, 256>>>(w4, wt4);
    quant_biases<<<1, 256>>>(b1, b2, b3, b4);
    prep_kernel<<<1, 1>>>(relus, dvds, bitsp);

    const int SM_RES = 324*400 + 4*2048 + 2*36*4;   // 138080
    cudaFuncSetAttribute(conv_res, cudaFuncAttributeMaxDynamicSharedMemorySize, SM_RES);

    // L1: 320ch 48x48 -> 192ch 96x96
    conv_mma<64,4,2,8,false><<<dim3(3, 6, 12), 256>>>(xh, h0, wt1, b1q, m0, 320, 192, 48, 48, 0);
    // L2: 192ch 96x96 -> 192ch 192x192
    conv_mma<64,4,2,16,false><<<dim3(6, 6, 12), 256>>>(h0, h1, wt2, b2q, m1, 192, 192, 96, 96, 1);
    // L3: 192ch 192x192 -> 192ch 384x384 (A-resident, 1 wave of 144 CTAs)
    conv_res<<<dim3(12, 12), 256, SM_RES>>>(h1, h2, wt3, b3q, m2, 192, 192);
    // L4: 192ch 384x384 -> 3ch 768x768, parity-folded N=16, f32 NCHW out
    conv_mma<16,8,1,16,true><<<dim3(24, 24, 1), 256>>>(h2, d_out, wt4, b4q, m3, 192, 3, 384, 384, 3);
}

// round 11
// speedup vs baseline: 1.1999x; 1.1999x over previous
#include <cuda_runtime.h>
#include <cuda_fp16.h>
#include <math.h>

typedef unsigned int u32;

// ---------------- static device scratch (allocation-free rule) ----------------
__device__ __half g_xh[48*48*320];            // L1 input NHWC fp16
__device__ __half g_h0[96*96*192];            // L1 out / L2 in
__device__ __half g_h1[192*192*192];          // L2 out / L3 in
__device__ __half g_h2[384*384*192];          // L3 out / L4 in
// B weight BLOBS: [z][chunk][tap9] x (NTILE rows x 32B), consumption order
__device__ __align__(256) __half g_wb1[12*20*9*64*16];
__device__ __align__(256) __half g_wb2[12*12*9*64*16];
__device__ __align__(256) __half g_wb3[12*12*9*64*16];
__device__ __align__(256) __half g_wb4[12*9*16*16];
__device__ float g_b1q[192];
__device__ float g_b2q[192];
__device__ float g_b3q[192];
__device__ float g_b4q[3];
__device__ float g_params[24];

// ---------------- PTX wrappers ----------------
#define CPASYNC(dst, src, sz) \
    asm volatile("cp.async.cg.shared.global [%0], [%1], 16, %2;" :: "r"(dst), "l"(src), "r"(sz))
#define CPCOMMIT() asm volatile("cp.async.commit_group;")
#define CPWAIT(n)  asm volatile("cp.async.wait_group %0;" :: "n"(n))
#define LDSM4(r0,r1,r2,r3,addr) \
    asm volatile("ldmatrix.sync.aligned.m8n8.x4.shared.b16 {%0,%1,%2,%3}, [%4];" \
        : "=r"(r0),"=r"(r1),"=r"(r2),"=r"(r3) : "r"(addr))
#define MMA16816(c0,c1,c2,c3,a0,a1,a2,a3,b0,b1) \
    asm volatile("mma.sync.aligned.m16n8k16.row.col.f32.f16.f16.f32 " \
        "{%0,%1,%2,%3}, {%4,%5,%6,%7}, {%8,%9}, {%0,%1,%2,%3};" \
        : "+f"(c0),"+f"(c1),"+f"(c2),"+f"(c3) \
        : "r"(a0),"r"(a1),"r"(a2),"r"(a3),"r"(b0),"r"(b1))
#define MBAR_INIT(mb, cnt) \
    asm volatile("mbarrier.init.shared.b64 [%0], %1;" :: "r"(mb), "r"(cnt) : "memory")
#define MBAR_EXPECT_TX(mb, bytes) \
    asm volatile("mbarrier.arrive.expect_tx.shared.b64 _, [%0], %1;" :: "r"(mb), "r"(bytes) : "memory")
#define TMA_BULK(dst, src, bytes, mb) \
    asm volatile("cp.async.bulk.shared::cluster.global.mbarrier::complete_tx::bytes [%0], [%1], %2, [%3];" \
        :: "r"(dst), "l"(src), "r"(bytes), "r"(mb) : "memory")
#define MBAR_WAIT(mb, parity) do { \
    u32 _done = 0; \
    while (!_done) { \
        asm volatile("{\n\t.reg .pred p;\n\t" \
            "mbarrier.try_wait.parity.acquire.cta.shared::cta.b64 p, [%1], %2;\n\t" \
            "selp.b32 %0, 1, 0, p;\n\t}" \
            : "=r"(_done) : "r"(mb), "r"(parity) : "memory"); \
    } \
} while(0)

// ---------------- small prep kernels ----------------
__global__ void quant_scalars(const float* __restrict__ b1, const float* __restrict__ b2,
                              const float* __restrict__ b3, const float* __restrict__ b4,
                              const float* __restrict__ relus, const int* __restrict__ dvds,
                              const int* __restrict__ bitsp) {
    int i = threadIdx.x;
    if (i < 192) {
        g_b1q[i] = rintf(b1[i]);
        g_b2q[i] = rintf(b2[i]);
        g_b3q[i] = rintf(b3[i]);
    }
    if (i < 3) g_b4q[i] = rintf(b4[i]);
    if (i == 224) {
        float B = bitsp ? (float)(*bitsp) : 8.0f;
        float maxv = exp2f(B) - 1.0f;
        const int sks[3] = {3, 4, 3};
        for (int k = 0; k < 3; k++) {
            float dv = (float)dvds[k];
            g_params[k*6+0] = exp2f(dv - 10.0f);
            g_params[k*6+1] = exp2f(9.0f - dv);
            g_params[k*6+2] = rintf((maxv / relus[k]) * 33554432.0f);
            float sk = (float)sks[k];
            g_params[k*6+3] = floorf((relus[k] + exp2f(sk - 1.0f)) * exp2f(-sk));
            g_params[k*6+4] = exp2f(24.0f - sk);
            g_params[k*6+5] = exp2f(sk - 25.0f);
        }
        float dv3 = (float)dvds[3];
        g_params[18] = exp2f(dv3 - 9.0f);
        g_params[19] = exp2f(8.0f - dv3);
    }
}

// NCHW f32 -> NHWC fp16 (values are small ints: exact)
__global__ void nchw2nhwc(const float* __restrict__ src, __half* __restrict__ dst,
                          int C, int HW) {
    int idx = blockIdx.x * blockDim.x + threadIdx.x;
    if (idx >= C * HW) return;
    int s = idx / C, c = idx % C;
    dst[idx] = __float2half_rn(src[c * HW + s]);
}

// Layers 1-3: w [CIN][192][5][5] f32 -> blobs [z=cog*4+p][chunk][tap][64 rows x 16ci].
// Block per (co, layer). Tap order matches conv: dy outer, dx inner, per parity.
__global__ void prep_wb3x(const float* __restrict__ w1, const float* __restrict__ w2,
                          const float* __restrict__ w3) {
    __shared__ float tile[320 * 25];
    const int which = blockIdx.y;
    const float* w = which == 0 ? w1 : (which == 1 ? w2 : w3);
    __half* wb     = which == 0 ? g_wb1 : (which == 1 ? g_wb2 : g_wb3);
    const int CIN  = which == 0 ? 320 : 192;
    const int COUT = 192;
    const int co = blockIdx.x;
    const int tid = threadIdx.x;
    for (int i = tid; i < CIN * 25; i += 256) {
        int ci = i / 25, t = i % 25;
        tile[i] = w[((size_t)ci * COUT + co) * 25 + t];
    }
    __syncthreads();
    const int nchk = CIN >> 4;
    const int n = co & 63, cog = co >> 6;
    for (int i = tid; i < 25 * nchk; i += 256) {
        int pt = i / nchk, chunk = i % nchk;
        int p, t;
        if (pt < 9)       { p = 0; t = pt; }
        else if (pt < 15) { p = 1; t = pt - 9; }
        else if (pt < 21) { p = 2; t = pt - 15; }
        else              { p = 3; t = pt - 21; }
        int py = p & 1, px = p >> 1;
        int ndx = px ? 2 : 3;
        int dy = (py ? 0 : -1) + t / ndx;
        int dx = (px ? 0 : -1) + t % ndx;
        int ky = py + 2 - 2 * dy, kx = px + 2 - 2 * dx;
        int z = cog * 4 + p;
        size_t blob = ((size_t)z * nchk + chunk) * 9 + t;
        __half h[16];
        #pragma unroll
        for (int j = 0; j < 16; j++)
            h[j] = __float2half_rn(rintf(tile[(chunk * 16 + j) * 25 + ky * 5 + kx]));
        uint4* dst = (uint4*)(wb + blob * 1024 + n * 16);
        dst[0] = ((uint4*)h)[0];
        dst[1] = ((uint4*)h)[1];
    }
}

// L4: w [192][3][5][5] -> blobs [chunk][tap9][16 rows x 16ci], n=(py*2+px)*4+co
__global__ void prep_wb4(const float* __restrict__ w) {
    int idx = blockIdx.x * blockDim.x + threadIdx.x;
    if (idx >= 12 * 9 * 16) return;
    int chunk = idx / 144;
    int r = idx % 144;
    int t = r / 16, n = r % 16;
    int dy = t / 3 - 1, dx = t % 3 - 1;
    int p = n >> 2, c = n & 3;
    int py = p >> 1, px = p & 1;
    __half h[16];
    #pragma unroll
    for (int j = 0; j < 16; j++) {
        float v = 0.f;
        if (c < 3 && (py == 0 || dy >= 0) && (px == 0 || dx >= 0)) {
            int ky = py + 2 - 2 * dy, kx = px + 2 - 2 * dx;
            v = rintf(w[((size_t)(chunk * 16 + j) * 3 + c) * 25 + ky * 5 + kx]);
        }
        h[j] = __float2half_rn(v);
    }
    uint4* dst = (uint4*)(g_wb4 + ((size_t)(chunk * 9 + t) * 16 + n) * 16);
    dst[0] = ((uint4*)h)[0];
    dst[1] = ((uint4*)h)[1];
}

// ---------------- tensor-core transposed conv: cp.async A + TMA-bulk B ----------
// CTA: (YR x 16) sites x NTILE output-n. 256 threads = 8 warps (WM x WN).
// A smem: [(YR+2) rows][18 cols][16 ci], 48B pitch, 2-stage ring (cp.async groups).
// B smem: 4 slots of NTILE x 32B packed blobs, filled by single-thread TMA bulk
// copies completing on a 4-mbarrier ring (phase (i>>2)&1), prefetch +3.
template<int NTILE, int WM, int WN, int YR, bool LAST>
__global__ void __launch_bounds__(256, 2) conv_mma(
    const __half* __restrict__ inA, void* __restrict__ outp,
    const __half* __restrict__ Wt, const float* __restrict__ bq,
    const float* __restrict__ mul,
    int CIN, int COUT, int H, int W, int stage)
{
    constexpr int MI = YR / WM;
    constexpr int NI = NTILE / (8 * WN);
    constexpr int NPAIR = NI / 2;
    constexpr int NSITES = (YR + 2) * 18;
    constexpr int ASTG = NSITES * 48;
    constexpr int BSTG = NTILE * 32;
    __shared__ __align__(16) char smem[2 * ASTG + 4 * BSTG];
    __shared__ __align__(8) unsigned long long mbarB[4];

    const int tid = threadIdx.x;
    const int lane = tid & 31, wid = tid >> 5;
    const int warp_m = wid % WM, warp_n = wid / WM;
    const int x0 = blockIdx.x * 16, y0 = blockIdx.y * YR;
    int py, px, co0;
    if (LAST) { py = 0; px = 0; co0 = 0; }
    else { py = blockIdx.z & 1; px = (blockIdx.z >> 1) & 1; co0 = (blockIdx.z >> 2) * 64; }

    // A tap offsets
    int ntaps, tAoff[9];
    if (LAST) {
        ntaps = 9;
        #pragma unroll
        for (int t = 0; t < 9; t++) tAoff[t] = ((t / 3) * 18 + (t % 3)) * 48;
    } else {
        ntaps = 0;
        for (int dy = (py ? 0 : -1); dy <= 1; dy++)
            for (int dx = (px ? 0 : -1); dx <= 1; dx++)
                tAoff[ntaps++] = ((dy + 1) * 18 + (dx + 1)) * 48;
    }
    const int nchunks = CIN >> 4;
    const int niter = nchunks * ntaps;
    const int zbase = (LAST ? 0 : blockIdx.z) * nchunks;

    const u32 smem_u = (u32)__cvta_generic_to_shared(smem);
    const u32 Abase = smem_u;
    const u32 Bbase = smem_u + 2 * ASTG;
    const u32 mbar_u = (u32)__cvta_generic_to_shared(mbarB);

    auto loadA = [&](int chunk, int slot) {
        const int ci0 = chunk << 4;
        #pragma unroll
        for (int k = 0; k < (NSITES * 2 + 255) / 256; k++) {
            int idx = tid + k * 256;
            if (idx < NSITES * 2) {
                int site = idx >> 1, seg = idx & 1;
                int r = site / 18, c = site % 18;
                int gy = y0 - 1 + r, gx = x0 - 1 + c;
                bool ok = (unsigned)gy < (unsigned)H && (unsigned)gx < (unsigned)W;
                const __half* src = ok ? (inA + ((size_t)(gy * W + gx) * CIN + ci0 + seg * 8)) : inA;
                u32 dst = Abase + slot * ASTG + site * 48 + seg * 16;
                CPASYNC(dst, src, ok ? 16 : 0);
            }
        }
    };
    auto issueB = [&](int tap, int chunk, int slot) {
        if (tid == 0) {
            u32 mb = mbar_u + slot * 8;
            MBAR_EXPECT_TX(mb, BSTG);
            const __half* src = Wt + ((size_t)(zbase + chunk) * 9 + tap) * (NTILE * 16);
            TMA_BULK(Bbase + slot * BSTG, src, BSTG, mb);
        }
    };

    // mbarrier init + prologue
    if (tid == 0) {
        #pragma unroll
        for (int s = 0; s < 4; s++) MBAR_INIT(mbar_u + s * 8, 1);
    }
    loadA(0, 0); CPCOMMIT();
    __syncthreads();                       // init visible before TMA arrives
    issueB(0, 0, 0);
    issueB(1, 0, 1);
    issueB(2, 0, 2);

    float acc[MI][NI][4];
    #pragma unroll
    for (int mi = 0; mi < MI; mi++)
        #pragma unroll
        for (int ni = 0; ni < NI; ni++)
            #pragma unroll
            for (int k = 0; k < 4; k++) acc[mi][ni][k] = 0.f;

    const int la = lane & 7, ms = lane >> 3;
    const u32 aoff_lane = (u32)((la + ((ms & 1) << 3)) * 48 + ((ms >> 1) << 4));
    const int rb = la + ((lane >> 4) << 3);
    const u32 boff_lane = (u32)(rb * 32 + (((lane >> 3) & 1) << 4));

    int cur_tap = 0, cur_chunk = 0;
    int pf_tap = 3, pf_chunk = 0;          // metadata for iter i+3 (ntaps>=4)

    for (int i = 0; i < niter; i++) {
        if (cur_tap == 0) CPWAIT(0);       // A(cur_chunk) resident (only A in groups)
        MBAR_WAIT(mbar_u + (i & 3) * 8, (i >> 2) & 1);
        __syncthreads();                   // slot (i-1)&3 fully consumed by all warps
        if (i + 3 < niter) issueB(pf_tap, pf_chunk, (i + 3) & 3);
        if (cur_tap == 0 && cur_chunk + 1 < nchunks) {
            loadA(cur_chunk + 1, (cur_chunk + 1) & 1);
            CPCOMMIT();
        }

        const u32 Astage = Abase + (cur_chunk & 1) * ASTG + tAoff[cur_tap] + aoff_lane;
        const u32 Bstage = Bbase + (i & 3) * BSTG + warp_n * (NI * 8 * 32) + boff_lane;

        u32 a[MI][4], b[NPAIR][4];
        #pragma unroll
        for (int mi = 0; mi < MI; mi++) {
            int ylocal = warp_m * MI + mi;
            LDSM4(a[mi][0], a[mi][1], a[mi][2], a[mi][3], Astage + ylocal * (18 * 48));
        }
        #pragma unroll
        for (int p2 = 0; p2 < NPAIR; p2++)
            LDSM4(b[p2][0], b[p2][1], b[p2][2], b[p2][3], Bstage + p2 * (16 * 32));

        #pragma unroll
        for (int mi = 0; mi < MI; mi++)
            #pragma unroll
            for (int ni = 0; ni < NI; ni++)
                MMA16816(acc[mi][ni][0], acc[mi][ni][1], acc[mi][ni][2], acc[mi][ni][3],
                         a[mi][0], a[mi][1], a[mi][2], a[mi][3],
                         b[ni >> 1][(ni & 1) * 2], b[ni >> 1][(ni & 1) * 2 + 1]);

        if (++cur_tap == ntaps) { cur_tap = 0; cur_chunk++; }
        if (++pf_tap == ntaps) { pf_tap = 0; pf_chunk++; }
    }

    // -------- quant epilogue --------
    float addA, invA, clpv = 0.f, sclv = 0.f, addB = 0.f, invB = 0.f;
    if (!LAST) {
        addA = g_params[stage*6+0]; invA = g_params[stage*6+1];
        clpv = g_params[stage*6+2]; sclv = g_params[stage*6+3];
        addB = g_params[stage*6+4]; invB = g_params[stage*6+5];
    } else {
        addA = g_params[18]; invA = g_params[19];
    }
    const int W2 = 2 * W;

    if (!LAST) {
        __half* out = (__half*)outp;
        #pragma unroll
        for (int mi = 0; mi < MI; mi++) {
            int ylocal = warp_m * MI + mi;
            int oy = 2 * (y0 + ylocal) + py;
            #pragma unroll
            for (int ni = 0; ni < NI; ni++) {
                int co = co0 + warp_n * (NI * 8) + ni * 8 + (lane & 3) * 2;
                float b0f = bq[co], b1f = bq[co + 1];
                float m0f = mul[co], m1f = mul[co + 1];
                #pragma unroll
                for (int h = 0; h < 2; h++) {
                    int xl = (lane >> 2) + h * 8;
                    int ox = 2 * (x0 + xl) + px;
                    float v0 = acc[mi][ni][h * 2 + 0];
                    float v1 = acc[mi][ni][h * 2 + 1];
                    v0 = floorf(((v0 + b0f) * m0f + addA) * invA);
                    v0 = fminf(fmaxf(v0, 0.f), clpv);
                    v0 = floorf((v0 * sclv + addB) * invB);
                    v1 = floorf(((v1 + b1f) * m1f + addA) * invA);
                    v1 = fminf(fmaxf(v1, 0.f), clpv);
                    v1 = floorf((v1 * sclv + addB) * invB);
                    __half2 hv = __floats2half2_rn(v0, v1);
                    *(__half2*)(out + ((size_t)oy * W2 + ox) * COUT + co) = hv;
                }
            }
        }
    } else {
        float* out = (float*)outp;
        const int PLANE = W2 * 2 * H;
        #pragma unroll
        for (int mi = 0; mi < MI; mi++) {
            int ylocal = warp_m * MI + mi;
            #pragma unroll
            for (int ni = 0; ni < NI; ni++) {
                int nbase = ni * 8 + (lane & 3) * 2;
                #pragma unroll
                for (int h = 0; h < 2; h++) {
                    int xl = (lane >> 2) + h * 8;
                    #pragma unroll
                    for (int j = 0; j < 2; j++) {
                        int n = nbase + j;
                        int p = n >> 2, c = n & 3;
                        if (c < 3) {
                            int pyy = p >> 1, pxx = p & 1;
                            int oy = 2 * (y0 + ylocal) + pyy;
                            int ox = 2 * (x0 + xl) + pxx;
                            float v = acc[mi][ni][h * 2 + j];
                            v = (v + bq[c]) * mul[c];
                            v = floorf((v + addA) * invA);
                            out[(size_t)c * PLANE + (size_t)oy * W2 + ox] = v / 255.0f;
                        }
                    }
                }
            }
        }
    }
}

// ---------------- host launcher (graph-capturable: kernel launches only) -------
extern "C" void kernel_launch(void* const* d_in, const int* in_sizes, int n_in,
                              void* d_out, int out_size)
{
    const float* x     = (const float*)d_in[0];
    const float* w1    = (const float*)d_in[1];
    const float* b1    = (const float*)d_in[2];
    const float* w2    = (const float*)d_in[3];
    const float* b2    = (const float*)d_in[4];
    const float* w3    = (const float*)d_in[5];
    const float* b3    = (const float*)d_in[6];
    const float* w4    = (const float*)d_in[7];
    const float* b4    = (const float*)d_in[8];
    const float* m0    = (const float*)d_in[9];
    const float* m1    = (const float*)d_in[10];
    const float* m2    = (const float*)d_in[11];
    const float* m3    = (const float*)d_in[12];
    const float* relus = (const float*)d_in[13];
    const int*   dvds  = (const int*)d_in[14];
    const int*   bitsp = (n_in > 15) ? (const int*)d_in[15] : nullptr;

    __half *xh, *h0, *h1, *h2, *wb1, *wb2, *wb3, *wb4;
    float *b1q, *b2q, *b3q, *b4q;
    cudaGetSymbolAddress((void**)&xh,  g_xh);
    cudaGetSymbolAddress((void**)&h0,  g_h0);
    cudaGetSymbolAddress((void**)&h1,  g_h1);
    cudaGetSymbolAddress((void**)&h2,  g_h2);
    cudaGetSymbolAddress((void**)&wb1, g_wb1);
    cudaGetSymbolAddress((void**)&wb2, g_wb2);
    cudaGetSymbolAddress((void**)&wb3, g_wb3);
    cudaGetSymbolAddress((void**)&wb4, g_wb4);
    cudaGetSymbolAddress((void**)&b1q, g_b1q);
    cudaGetSymbolAddress((void**)&b2q, g_b2q);
    cudaGetSymbolAddress((void**)&b3q, g_b3q);
    cudaGetSymbolAddress((void**)&b4q, g_b4q);

    nchw2nhwc<<<(48*48*320 + 255)/256, 256>>>(x, xh, 320, 48*48);
    prep_wb3x<<<dim3(192, 3), 256>>>(w1, w2, w3);
    prep_wb4<<<(12*9*16 + 255)/256, 256>>>(w4);
    quant_scalars<<<1, 256>>>(b1, b2, b3, b4, relus, dvds, bitsp);

    // L1: 320ch 48x48 -> 192ch 96x96
    conv_mma<64,4,2,8,false><<<dim3(3, 6, 12), 256>>>(xh, h0, wb1, b1q, m0, 320, 192, 48, 48, 0);
    // L2: 192ch 96x96 -> 192ch 192x192
    conv_mma<64,4,2,16,false><<<dim3(6, 6, 12), 256>>>(h0, h1, wb2, b2q, m1, 192, 192, 96, 96, 1);
    // L3: 192ch 192x192 -> 192ch 384x384
    conv_mma<64,4,2,16,false><<<dim3(12, 12, 12), 256>>>(h1, h2, wb3, b3q, m2, 192, 192, 192, 192, 2);
    // L4: 192ch 384x384 -> 3ch 768x768, parity-folded N=16, f32 NCHW out
    conv_mma<16,8,1,16,true><<<dim3(24, 24, 1), 256>>>(h2, d_out, wb4, b4q, m3, 192, 3, 384, 384, 3);
}

// round 12
// speedup vs baseline: 1.2028x; 1.0024x over previous
#include <cuda_runtime.h>
#include <cuda_fp16.h>
#include <math.h>

typedef unsigned int u32;

// ---------------- static device scratch (allocation-free rule) ----------------
__device__ __half g_xh[48*48*320];            // L1 input NHWC fp16
__device__ __half g_h0[96*96*192];            // L1 out / L2 in
__device__ __half g_h1[192*192*192];          // L2 out / L3 in
__device__ __half g_h2[384*384*192];          // L3 out / L4 in
// B weight BLOBS: [z][chunk][tap9] x (NTILE rows x 32B), consumption order
__device__ __align__(256) __half g_wb1[12*20*9*64*16];
__device__ __align__(256) __half g_wb2[12*12*9*64*16];
__device__ __align__(256) __half g_wb3[12*12*9*64*16];
__device__ __align__(256) __half g_wb4[12*9*16*16];
__device__ float g_b1q[192];
__device__ float g_b2q[192];
__device__ float g_b3q[192];
__device__ float g_b4q[3];
__device__ float g_params[24];

// ---------------- PTX wrappers ----------------
#define CPASYNC(dst, src, sz) \
    asm volatile("cp.async.cg.shared.global [%0], [%1], 16, %2;" :: "r"(dst), "l"(src), "r"(sz))
#define CPCOMMIT() asm volatile("cp.async.commit_group;")
#define CPWAIT(n)  asm volatile("cp.async.wait_group %0;" :: "n"(n))
#define LDSM4(r0,r1,r2,r3,addr) \
    asm volatile("ldmatrix.sync.aligned.m8n8.x4.shared.b16 {%0,%1,%2,%3}, [%4];" \
        : "=r"(r0),"=r"(r1),"=r"(r2),"=r"(r3) : "r"(addr))
#define MMA16816(c0,c1,c2,c3,a0,a1,a2,a3,b0,b1) \
    asm volatile("mma.sync.aligned.m16n8k16.row.col.f32.f16.f16.f32 " \
        "{%0,%1,%2,%3}, {%4,%5,%6,%7}, {%8,%9}, {%0,%1,%2,%3};" \
        : "+f"(c0),"+f"(c1),"+f"(c2),"+f"(c3) \
        : "r"(a0),"r"(a1),"r"(a2),"r"(a3),"r"(b0),"r"(b1))
#define MBAR_INIT(mb, cnt) \
    asm volatile("mbarrier.init.shared.b64 [%0], %1;" :: "r"(mb), "r"(cnt) : "memory")
#define MBAR_EXPECT_TX(mb, bytes) \
    asm volatile("mbarrier.arrive.expect_tx.shared.b64 _, [%0], %1;" :: "r"(mb), "r"(bytes) : "memory")
#define TMA_BULK(dst, src, bytes, mb) \
    asm volatile("cp.async.bulk.shared::cluster.global.mbarrier::complete_tx::bytes [%0], [%1], %2, [%3];" \
        :: "r"(dst), "l"(src), "r"(bytes), "r"(mb) : "memory")
#define MBAR_WAIT(mb, parity) do { \
    u32 _done = 0; \
    while (!_done) { \
        asm volatile("{\n\t.reg .pred p;\n\t" \
            "mbarrier.try_wait.parity.acquire.cta.shared::cta.b64 p, [%1], %2;\n\t" \
            "selp.b32 %0, 1, 0, p;\n\t}" \
            : "=r"(_done) : "r"(mb), "r"(parity) : "memory"); \
    } \
} while(0)

// ---------------- small prep kernels ----------------
__global__ void quant_scalars(const float* __restrict__ b1, const float* __restrict__ b2,
                              const float* __restrict__ b3, const float* __restrict__ b4,
                              const float* __restrict__ relus, const int* __restrict__ dvds,
                              const int* __restrict__ bitsp) {
    int i = threadIdx.x;
    if (i < 192) {
        g_b1q[i] = rintf(b1[i]);
        g_b2q[i] = rintf(b2[i]);
        g_b3q[i] = rintf(b3[i]);
    }
    if (i < 3) g_b4q[i] = rintf(b4[i]);
    if (i == 224) {
        float B = bitsp ? (float)(*bitsp) : 8.0f;
        float maxv = exp2f(B) - 1.0f;
        const int sks[3] = {3, 4, 3};
        for (int k = 0; k < 3; k++) {
            float dv = (float)dvds[k];
            g_params[k*6+0] = exp2f(dv - 10.0f);
            g_params[k*6+1] = exp2f(9.0f - dv);
            g_params[k*6+2] = rintf((maxv / relus[k]) * 33554432.0f);
            float sk = (float)sks[k];
            g_params[k*6+3] = floorf((relus[k] + exp2f(sk - 1.0f)) * exp2f(-sk));
            g_params[k*6+4] = exp2f(24.0f - sk);
            g_params[k*6+5] = exp2f(sk - 25.0f);
        }
        float dv3 = (float)dvds[3];
        g_params[18] = exp2f(dv3 - 9.0f);
        g_params[19] = exp2f(8.0f - dv3);
    }
}

// NCHW f32 -> NHWC fp16 (values are small ints: exact)
__global__ void nchw2nhwc(const float* __restrict__ src, __half* __restrict__ dst,
                          int C, int HW) {
    int idx = blockIdx.x * blockDim.x + threadIdx.x;
    if (idx >= C * HW) return;
    int s = idx / C, c = idx % C;
    dst[idx] = __float2half_rn(src[c * HW + s]);
}

// Layers 1-3: w [CIN][192][5][5] f32 -> blobs [z=cog*4+p][chunk][tap][64 rows x 16ci].
// Block per (co, layer). Tap order matches conv: dy outer, dx inner, per parity.
__global__ void prep_wb3x(const float* __restrict__ w1, const float* __restrict__ w2,
                          const float* __restrict__ w3) {
    __shared__ float tile[320 * 25];
    const int which = blockIdx.y;
    const float* w = which == 0 ? w1 : (which == 1 ? w2 : w3);
    __half* wb     = which == 0 ? g_wb1 : (which == 1 ? g_wb2 : g_wb3);
    const int CIN  = which == 0 ? 320 : 192;
    const int COUT = 192;
    const int co = blockIdx.x;
    const int tid = threadIdx.x;
    for (int i = tid; i < CIN * 25; i += 256) {
        int ci = i / 25, t = i % 25;
        tile[i] = w[((size_t)ci * COUT + co) * 25 + t];
    }
    __syncthreads();
    const int nchk = CIN >> 4;
    const int n = co & 63, cog = co >> 6;
    for (int i = tid; i < 25 * nchk; i += 256) {
        int pt = i / nchk, chunk = i % nchk;
        int p, t;
        if (pt < 9)       { p = 0; t = pt; }
        else if (pt < 15) { p = 1; t = pt - 9; }
        else if (pt < 21) { p = 2; t = pt - 15; }
        else              { p = 3; t = pt - 21; }
        int py = p & 1, px = p >> 1;
        int ndx = px ? 2 : 3;
        int dy = (py ? 0 : -1) + t / ndx;
        int dx = (px ? 0 : -1) + t % ndx;
        int ky = py + 2 - 2 * dy, kx = px + 2 - 2 * dx;
        int z = cog * 4 + p;
        size_t blob = ((size_t)z * nchk + chunk) * 9 + t;
        __half h[16];
        #pragma unroll
        for (int j = 0; j < 16; j++)
            h[j] = __float2half_rn(rintf(tile[(chunk * 16 + j) * 25 + ky * 5 + kx]));
        uint4* dst = (uint4*)(wb + blob * 1024 + n * 16);
        dst[0] = ((uint4*)h)[0];
        dst[1] = ((uint4*)h)[1];
    }
}

// L4: w [192][3][5][5] -> blobs [chunk][tap9][16 rows x 16ci], n=(py*2+px)*4+co
__global__ void prep_wb4(const float* __restrict__ w) {
    int idx = blockIdx.x * blockDim.x + threadIdx.x;
    if (idx >= 12 * 9 * 16) return;
    int chunk = idx / 144;
    int r = idx % 144;
    int t = r / 16, n = r % 16;
    int dy = t / 3 - 1, dx = t % 3 - 1;
    int p = n >> 2, c = n & 3;
    int py = p >> 1, px = p & 1;
    __half h[16];
    #pragma unroll
    for (int j = 0; j < 16; j++) {
        float v = 0.f;
        if (c < 3 && (py == 0 || dy >= 0) && (px == 0 || dx >= 0)) {
            int ky = py + 2 - 2 * dy, kx = px + 2 - 2 * dx;
            v = rintf(w[((size_t)(chunk * 16 + j) * 3 + c) * 25 + ky * 5 + kx]);
        }
        h[j] = __float2half_rn(v);
    }
    uint4* dst = (uint4*)(g_wb4 + ((size_t)(chunk * 9 + t) * 16 + n) * 16);
    dst[0] = ((uint4*)h)[0];
    dst[1] = ((uint4*)h)[1];
}

// ---------------- tensor-core transposed conv: cp.async A + TMA-bulk B ----------
// CTA: (YR x 16) sites x NTILE output-n. 256 threads = 8 warps (WM x WN).
// A smem: [(YR+2) rows][18 cols][16 ci], 48B pitch, 2-stage ring (cp.async groups).
// B smem: 4 slots of NTILE x 32B packed blobs, filled by single-thread TMA bulk
// copies completing on a 4-mbarrier ring (phase (i>>2)&1), prefetch +3.
template<int NTILE, int WM, int WN, int YR, bool LAST>
__global__ void __launch_bounds__(256, 2) conv_mma(
    const __half* __restrict__ inA, void* __restrict__ outp,
    const __half* __restrict__ Wt, const float* __restrict__ bq,
    const float* __restrict__ mul,
    int CIN, int COUT, int H, int W, int stage)
{
    constexpr int MI = YR / WM;
    constexpr int NI = NTILE / (8 * WN);
    constexpr int NPAIR = NI / 2;
    constexpr int NSITES = (YR + 2) * 18;
    constexpr int ASTG = NSITES * 48;
    constexpr int BSTG = NTILE * 32;
    __shared__ __align__(16) char smem[2 * ASTG + 4 * BSTG];
    __shared__ __align__(8) unsigned long long mbarB[4];

    const int tid = threadIdx.x;
    const int lane = tid & 31, wid = tid >> 5;
    const int warp_m = wid % WM, warp_n = wid / WM;
    const int x0 = blockIdx.x * 16, y0 = blockIdx.y * YR;
    int py, px, co0;
    if (LAST) { py = 0; px = 0; co0 = 0; }
    else { py = blockIdx.z & 1; px = (blockIdx.z >> 1) & 1; co0 = (blockIdx.z >> 2) * 64; }

    // A tap offsets
    int ntaps, tAoff[9];
    if (LAST) {
        ntaps = 9;
        #pragma unroll
        for (int t = 0; t < 9; t++) tAoff[t] = ((t / 3) * 18 + (t % 3)) * 48;
    } else {
        ntaps = 0;
        for (int dy = (py ? 0 : -1); dy <= 1; dy++)
            for (int dx = (px ? 0 : -1); dx <= 1; dx++)
                tAoff[ntaps++] = ((dy + 1) * 18 + (dx + 1)) * 48;
    }
    const int nchunks = CIN >> 4;
    const int niter = nchunks * ntaps;
    const int zbase = (LAST ? 0 : blockIdx.z) * nchunks;

    const u32 smem_u = (u32)__cvta_generic_to_shared(smem);
    const u32 Abase = smem_u;
    const u32 Bbase = smem_u + 2 * ASTG;
    const u32 mbar_u = (u32)__cvta_generic_to_shared(mbarB);

    auto loadA = [&](int chunk, int slot) {
        const int ci0 = chunk << 4;
        #pragma unroll
        for (int k = 0; k < (NSITES * 2 + 255) / 256; k++) {
            int idx = tid + k * 256;
            if (idx < NSITES * 2) {
                int site = idx >> 1, seg = idx & 1;
                int r = site / 18, c = site % 18;
                int gy = y0 - 1 + r, gx = x0 - 1 + c;
                bool ok = (unsigned)gy < (unsigned)H && (unsigned)gx < (unsigned)W;
                const __half* src = ok ? (inA + ((size_t)(gy * W + gx) * CIN + ci0 + seg * 8)) : inA;
                u32 dst = Abase + slot * ASTG + site * 48 + seg * 16;
                CPASYNC(dst, src, ok ? 16 : 0);
            }
        }
    };
    auto issueB = [&](int tap, int chunk, int slot) {
        if (tid == 0) {
            u32 mb = mbar_u + slot * 8;
            MBAR_EXPECT_TX(mb, BSTG);
            const __half* src = Wt + ((size_t)(zbase + chunk) * 9 + tap) * (NTILE * 16);
            TMA_BULK(Bbase + slot * BSTG, src, BSTG, mb);
        }
    };

    // mbarrier init + prologue
    if (tid == 0) {
        #pragma unroll
        for (int s = 0; s < 4; s++) MBAR_INIT(mbar_u + s * 8, 1);
    }
    loadA(0, 0); CPCOMMIT();
    __syncthreads();                       // init visible before TMA arrives
    issueB(0, 0, 0);
    issueB(1, 0, 1);
    issueB(2, 0, 2);

    float acc[MI][NI][4];
    #pragma unroll
    for (int mi = 0; mi < MI; mi++)
        #pragma unroll
        for (int ni = 0; ni < NI; ni++)
            #pragma unroll
            for (int k = 0; k < 4; k++) acc[mi][ni][k] = 0.f;

    const int la = lane & 7, ms = lane >> 3;
    const u32 aoff_lane = (u32)((la + ((ms & 1) << 3)) * 48 + ((ms >> 1) << 4));
    const int rb = la + ((lane >> 4) << 3);
    const u32 boff_lane = (u32)(rb * 32 + (((lane >> 3) & 1) << 4));

    int cur_tap = 0, cur_chunk = 0;
    int pf_tap = 3, pf_chunk = 0;          // metadata for iter i+3 (ntaps>=4)

    for (int i = 0; i < niter; i++) {
        if (cur_tap == 0) CPWAIT(0);       // A(cur_chunk) resident (only A in groups)
        MBAR_WAIT(mbar_u + (i & 3) * 8, (i >> 2) & 1);
        __syncthreads();                   // slot (i-1)&3 fully consumed by all warps
        if (i + 3 < niter) issueB(pf_tap, pf_chunk, (i + 3) & 3);
        if (cur_tap == 0 && cur_chunk + 1 < nchunks) {
            loadA(cur_chunk + 1, (cur_chunk + 1) & 1);
            CPCOMMIT();
        }

        const u32 Astage = Abase + (cur_chunk & 1) * ASTG + tAoff[cur_tap] + aoff_lane;
        const u32 Bstage = Bbase + (i & 3) * BSTG + warp_n * (NI * 8 * 32) + boff_lane;

        u32 a[MI][4], b[NPAIR][4];
        #pragma unroll
        for (int mi = 0; mi < MI; mi++) {
            int ylocal = warp_m * MI + mi;
            LDSM4(a[mi][0], a[mi][1], a[mi][2], a[mi][3], Astage + ylocal * (18 * 48));
        }
        #pragma unroll
        for (int p2 = 0; p2 < NPAIR; p2++)
            LDSM4(b[p2][0], b[p2][1], b[p2][2], b[p2][3], Bstage + p2 * (16 * 32));

        #pragma unroll
        for (int mi = 0; mi < MI; mi++)
            #pragma unroll
            for (int ni = 0; ni < NI; ni++)
                MMA16816(acc[mi][ni][0], acc[mi][ni][1], acc[mi][ni][2], acc[mi][ni][3],
                         a[mi][0], a[mi][1], a[mi][2], a[mi][3],
                         b[ni >> 1][(ni & 1) * 2], b[ni >> 1][(ni & 1) * 2 + 1]);

        if (++cur_tap == ntaps) { cur_tap = 0; cur_chunk++; }
        if (++pf_tap == ntaps) { pf_tap = 0; pf_chunk++; }
    }

    // -------- quant epilogue --------
    float addA, invA, clpv = 0.f, sclv = 0.f, addB = 0.f, invB = 0.f;
    if (!LAST) {
        addA = g_params[stage*6+0]; invA = g_params[stage*6+1];
        clpv = g_params[stage*6+2]; sclv = g_params[stage*6+3];
        addB = g_params[stage*6+4]; invB = g_params[stage*6+5];
    } else {
        addA = g_params[18]; invA = g_params[19];
    }
    const int W2 = 2 * W;

    if (!LAST) {
        __half* out = (__half*)outp;
        #pragma unroll
        for (int mi = 0; mi < MI; mi++) {
            int ylocal = warp_m * MI + mi;
            int oy = 2 * (y0 + ylocal) + py;
            #pragma unroll
            for (int ni = 0; ni < NI; ni++) {
                int co = co0 + warp_n * (NI * 8) + ni * 8 + (lane & 3) * 2;
                float b0f = bq[co], b1f = bq[co + 1];
                float m0f = mul[co], m1f = mul[co + 1];
                #pragma unroll
                for (int h = 0; h < 2; h++) {
                    int xl = (lane >> 2) + h * 8;
                    int ox = 2 * (x0 + xl) + px;
                    float v0 = acc[mi][ni][h * 2 + 0];
                    float v1 = acc[mi][ni][h * 2 + 1];
                    v0 = floorf(((v0 + b0f) * m0f + addA) * invA);
                    v0 = fminf(fmaxf(v0, 0.f), clpv);
                    v0 = floorf((v0 * sclv + addB) * invB);
                    v1 = floorf(((v1 + b1f) * m1f + addA) * invA);
                    v1 = fminf(fmaxf(v1, 0.f), clpv);
                    v1 = floorf((v1 * sclv + addB) * invB);
                    __half2 hv = __floats2half2_rn(v0, v1);
                    *(__half2*)(out + ((size_t)oy * W2 + ox) * COUT + co) = hv;
                }
            }
        }
    } else {
        float* out = (float*)outp;
        const int PLANE = W2 * 2 * H;
        #pragma unroll
        for (int mi = 0; mi < MI; mi++) {
            int ylocal = warp_m * MI + mi;
            #pragma unroll
            for (int ni = 0; ni < NI; ni++) {
                int nbase = ni * 8 + (lane & 3) * 2;
                #pragma unroll
                for (int h = 0; h < 2; h++) {
                    int xl = (lane >> 2) + h * 8;
                    #pragma unroll
                    for (int j = 0; j < 2; j++) {
                        int n = nbase + j;
                        int p = n >> 2, c = n & 3;
                        if (c < 3) {
                            int pyy = p >> 1, pxx = p & 1;
                            int oy = 2 * (y0 + ylocal) + pyy;
                            int ox = 2 * (x0 + xl) + pxx;
                            float v = acc[mi][ni][h * 2 + j];
                            v = (v + bq[c]) * mul[c];
                            v = floorf((v + addA) * invA);
                            out[(size_t)c * PLANE + (size_t)oy * W2 + ox] = v / 255.0f;
                        }
                    }
                }
            }
        }
    }
}

// ---------------- host launcher (graph-capturable: kernel launches only) -------
extern "C" void kernel_launch(void* const* d_in, const int* in_sizes, int n_in,
                              void* d_out, int out_size)
{
    const float* x     = (const float*)d_in[0];
    const float* w1    = (const float*)d_in[1];
    const float* b1    = (const float*)d_in[2];
    const float* w2    = (const float*)d_in[3];
    const float* b2    = (const float*)d_in[4];
    const float* w3    = (const float*)d_in[5];
    const float* b3    = (const float*)d_in[6];
    const float* w4    = (const float*)d_in[7];
    const float* b4    = (const float*)d_in[8];
    const float* m0    = (const float*)d_in[9];
    const float* m1    = (const float*)d_in[10];
    const float* m2    = (const float*)d_in[11];
    const float* m3    = (const float*)d_in[12];
    const float* relus = (const float*)d_in[13];
    const int*   dvds  = (const int*)d_in[14];
    const int*   bitsp = (n_in > 15) ? (const int*)d_in[15] : nullptr;

    __half *xh, *h0, *h1, *h2, *wb1, *wb2, *wb3, *wb4;
    float *b1q, *b2q, *b3q, *b4q;
    cudaGetSymbolAddress((void**)&xh,  g_xh);
    cudaGetSymbolAddress((void**)&h0,  g_h0);
    cudaGetSymbolAddress((void**)&h1,  g_h1);
    cudaGetSymbolAddress((void**)&h2,  g_h2);
    cudaGetSymbolAddress((void**)&wb1, g_wb1);
    cudaGetSymbolAddress((void**)&wb2, g_wb2);
    cudaGetSymbolAddress((void**)&wb3, g_wb3);
    cudaGetSymbolAddress((void**)&wb4, g_wb4);
    cudaGetSymbolAddress((void**)&b1q, g_b1q);
    cudaGetSymbolAddress((void**)&b2q, g_b2q);
    cudaGetSymbolAddress((void**)&b3q, g_b3q);
    cudaGetSymbolAddress((void**)&b4q, g_b4q);

    nchw2nhwc<<<(48*48*320 + 255)/256, 256>>>(x, xh, 320, 48*48);
    prep_wb3x<<<dim3(192, 3), 256>>>(w1, w2, w3);
    prep_wb4<<<(12*9*16 + 255)/256, 256>>>(w4);
    quant_scalars<<<1, 256>>>(b1, b2, b3, b4, relus, dvds, bitsp);

    // L1: 320ch 48x48 -> 192ch 96x96
    conv_mma<64,4,2,8,false><<<dim3(3, 6, 12), 256>>>(xh, h0, wb1, b1q, m0, 320, 192, 48, 48, 0);
    // L2: 192ch 96x96 -> 192ch 192x192
    conv_mma<64,4,2,16,false><<<dim3(6, 6, 12), 256>>>(h0, h1, wb2, b2q, m1, 192, 192, 96, 96, 1);
    // L3: 192ch 192x192 -> 192ch 384x384
    conv_mma<64,4,2,16,false><<<dim3(12, 12, 12), 256>>>(h1, h2, wb3, b3q, m2, 192, 192, 192, 192, 2);
    // L4: 192ch 384x384 -> 3ch 768x768, parity-folded N=16, f32 NCHW out
    conv_mma<16,8,1,16,true><<<dim3(24, 24, 1), 256>>>(h2, d_out, wb4, b4q, m3, 192, 3, 384, 384, 3);
}

// round 14
// speedup vs baseline: 1.2591x; 1.0469x over previous
#include <cuda_runtime.h>
#include <cuda_fp16.h>
#include <math.h>

typedef unsigned int u32;

// ---------------- static device scratch (allocation-free rule) ----------------
__device__ __half g_xh[48*48*320];            // L1 input NHWC fp16
__device__ __half g_h0[96*96*192];            // L1 out / L2 in
__device__ __half g_h1[192*192*192];          // L2 out / L3 in
__device__ __half g_h2[384*384*192];          // L3 out / L4 in
// B weight BLOBS: [z][chunk][tap9] x (NTILE rows x 32B), consumption order
__device__ __align__(256) __half g_wb1[12*20*9*64*16];
__device__ __align__(256) __half g_wb2[12*12*9*64*16];
__device__ __align__(256) __half g_wb3[12*12*9*64*16];
__device__ __align__(256) __half g_wb4[12*9*16*16];
__device__ float g_b1q[192];
__device__ float g_b2q[192];
__device__ float g_b3q[192];
__device__ float g_b4q[3];
__device__ float g_params[24];

// ---------------- PTX wrappers ----------------
#define CPASYNC(dst, src, sz) \
    asm volatile("cp.async.cg.shared.global [%0], [%1], 16, %2;" :: "r"(dst), "l"(src), "r"(sz))
#define CPCOMMIT() asm volatile("cp.async.commit_group;")
#define CPWAIT(n)  asm volatile("cp.async.wait_group %0;" :: "n"(n))
#define LDSM4(r0,r1,r2,r3,addr) \
    asm volatile("ldmatrix.sync.aligned.m8n8.x4.shared.b16 {%0,%1,%2,%3}, [%4];" \
        : "=r"(r0),"=r"(r1),"=r"(r2),"=r"(r3) : "r"(addr))
#define MMA16816(c0,c1,c2,c3,a0,a1,a2,a3,b0,b1) \
    asm volatile("mma.sync.aligned.m16n8k16.row.col.f32.f16.f16.f32 " \
        "{%0,%1,%2,%3}, {%4,%5,%6,%7}, {%8,%9}, {%0,%1,%2,%3};" \
        : "+f"(c0),"+f"(c1),"+f"(c2),"+f"(c3) \
        : "r"(a0),"r"(a1),"r"(a2),"r"(a3),"r"(b0),"r"(b1))
#define MBAR_INIT(mb, cnt) \
    asm volatile("mbarrier.init.shared.b64 [%0], %1;" :: "r"(mb), "r"(cnt) : "memory")
#define MBAR_EXPECT_TX(mb, bytes) \
    asm volatile("mbarrier.arrive.expect_tx.shared.b64 _, [%0], %1;" :: "r"(mb), "r"(bytes) : "memory")
#define TMA_BULK(dst, src, bytes, mb) \
    asm volatile("cp.async.bulk.shared::cluster.global.mbarrier::complete_tx::bytes [%0], [%1], %2, [%3];" \
        :: "r"(dst), "l"(src), "r"(bytes), "r"(mb) : "memory")
#define MBAR_WAIT(mb, parity) do { \
    u32 _done = 0; \
    while (!_done) { \
        asm volatile("{\n\t.reg .pred p;\n\t" \
            "mbarrier.try_wait.parity.acquire.cta.shared::cta.b64 p, [%1], %2;\n\t" \
            "selp.b32 %0, 1, 0, p;\n\t}" \
            : "=r"(_done) : "r"(mb), "r"(parity) : "memory"); \
    } \
} while(0)

// ---------------- small prep kernels ----------------
__global__ void quant_scalars(const float* __restrict__ b1, const float* __restrict__ b2,
                              const float* __restrict__ b3, const float* __restrict__ b4,
                              const float* __restrict__ relus, const int* __restrict__ dvds,
                              const int* __restrict__ bitsp) {
    int i = threadIdx.x;
    if (i < 192) {
        g_b1q[i] = rintf(b1[i]);
        g_b2q[i] = rintf(b2[i]);
        g_b3q[i] = rintf(b3[i]);
    }
    if (i < 3) g_b4q[i] = rintf(b4[i]);
    if (i == 224) {
        float B = bitsp ? (float)(*bitsp) : 8.0f;
        float maxv = exp2f(B) - 1.0f;
        const int sks[3] = {3, 4, 3};
        for (int k = 0; k < 3; k++) {
            float dv = (float)dvds[k];
            g_params[k*6+0] = exp2f(dv - 10.0f);
            g_params[k*6+1] = exp2f(9.0f - dv);
            g_params[k*6+2] = rintf((maxv / relus[k]) * 33554432.0f);
            float sk = (float)sks[k];
            g_params[k*6+3] = floorf((relus[k] + exp2f(sk - 1.0f)) * exp2f(-sk));
            g_params[k*6+4] = exp2f(24.0f - sk);
            g_params[k*6+5] = exp2f(sk - 25.0f);
        }
        float dv3 = (float)dvds[3];
        g_params[18] = exp2f(dv3 - 9.0f);
        g_params[19] = exp2f(8.0f - dv3);
    }
}

// NCHW f32 -> NHWC fp16 (values are small ints: exact)
__global__ void nchw2nhwc(const float* __restrict__ src, __half* __restrict__ dst,
                          int C, int HW) {
    int idx = blockIdx.x * blockDim.x + threadIdx.x;
    if (idx >= C * HW) return;
    int s = idx / C, c = idx % C;
    dst[idx] = __float2half_rn(src[c * HW + s]);
}

// Layers 1-3: w [CIN][192][5][5] f32 -> blobs [z=cog*4+p][chunk][tap][64 rows x 16ci].
__global__ void prep_wb3x(const float* __restrict__ w1, const float* __restrict__ w2,
                          const float* __restrict__ w3) {
    __shared__ float tile[320 * 25];
    const int which = blockIdx.y;
    const float* w = which == 0 ? w1 : (which == 1 ? w2 : w3);
    __half* wb     = which == 0 ? g_wb1 : (which == 1 ? g_wb2 : g_wb3);
    const int CIN  = which == 0 ? 320 : 192;
    const int COUT = 192;
    const int co = blockIdx.x;
    const int tid = threadIdx.x;
    for (int i = tid; i < CIN * 25; i += 256) {
        int ci = i / 25, t = i % 25;
        tile[i] = w[((size_t)ci * COUT + co) * 25 + t];
    }
    __syncthreads();
    const int nchk = CIN >> 4;
    const int n = co & 63, cog = co >> 6;
    for (int i = tid; i < 25 * nchk; i += 256) {
        int pt = i / nchk, chunk = i % nchk;
        int p, t;
        if (pt < 9)       { p = 0; t = pt; }
        else if (pt < 15) { p = 1; t = pt - 9; }
        else if (pt < 21) { p = 2; t = pt - 15; }
        else              { p = 3; t = pt - 21; }
        int py = p & 1, px = p >> 1;
        int ndx = px ? 2 : 3;
        int dy = (py ? 0 : -1) + t / ndx;
        int dx = (px ? 0 : -1) + t % ndx;
        int ky = py + 2 - 2 * dy, kx = px + 2 - 2 * dx;
        int z = cog * 4 + p;
        size_t blob = ((size_t)z * nchk + chunk) * 9 + t;
        __half h[16];
        #pragma unroll
        for (int j = 0; j < 16; j++)
            h[j] = __float2half_rn(rintf(tile[(chunk * 16 + j) * 25 + ky * 5 + kx]));
        uint4* dst = (uint4*)(wb + blob * 1024 + n * 16);
        dst[0] = ((uint4*)h)[0];
        dst[1] = ((uint4*)h)[1];
    }
}

// L4: w [192][3][5][5] -> blobs [chunk][tap9][16 rows x 16ci], n=(py*2+px)*4+co
__global__ void prep_wb4(const float* __restrict__ w) {
    int idx = blockIdx.x * blockDim.x + threadIdx.x;
    if (idx >= 12 * 9 * 16) return;
    int chunk = idx / 144;
    int r = idx % 144;
    int t = r / 16, n = r % 16;
    int dy = t / 3 - 1, dx = t % 3 - 1;
    int p = n >> 2, c = n & 3;
    int py = p >> 1, px = p & 1;
    __half h[16];
    #pragma unroll
    for (int j = 0; j < 16; j++) {
        float v = 0.f;
        if (c < 3 && (py == 0 || dy >= 0) && (px == 0 || dx >= 0)) {
            int ky = py + 2 - 2 * dy, kx = px + 2 - 2 * dx;
            v = rintf(w[((size_t)(chunk * 16 + j) * 3 + c) * 25 + ky * 5 + kx]);
        }
        h[j] = __float2half_rn(v);
    }
    uint4* dst = (uint4*)(g_wb4 + ((size_t)(chunk * 9 + t) * 16 + n) * 16);
    dst[0] = ((uint4*)h)[0];
    dst[1] = ((uint4*)h)[1];
}

// ---------------- tensor-core transposed conv: paired iterations ---------------
// CTA: (YR x 16) sites x NTILE output-n. 256 threads = 8 warps (WM x WN).
// A smem: [(YR+2) rows][18 cols][16 ci], 48B pitch, 2-stage ring (cp.async).
// B smem: 6 slots of NTILE x 32B packed blobs via TMA bulk, slot = i mod 6,
// phase = (i/6)&1. TWO taps (B stages) consumed per __syncthreads.
template<int NTILE, int WM, int WN, int YR, bool LAST>
__global__ void __launch_bounds__(256, 2) conv_mma(
    const __half* __restrict__ inA, void* __restrict__ outp,
    const __half* __restrict__ Wt, const float* __restrict__ bq,
    const float* __restrict__ mul,
    int CIN, int COUT, int H, int W, int stage)
{
    constexpr int MI = YR / WM;
    constexpr int NI = NTILE / (8 * WN);
    constexpr int NPAIR = NI / 2;
    constexpr int NSITES = (YR + 2) * 18;
    constexpr int ASTG = NSITES * 48;
    constexpr int BSTG = NTILE * 32;
    __shared__ __align__(16) char smem[2 * ASTG + 6 * BSTG];
    __shared__ __align__(8) unsigned long long mbarB[6];

    const int tid = threadIdx.x;
    const int lane = tid & 31, wid = tid >> 5;
    const int warp_m = wid % WM, warp_n = wid / WM;
    const int x0 = blockIdx.x * 16, y0 = blockIdx.y * YR;
    int py, px, co0;
    if (LAST) { py = 0; px = 0; co0 = 0; }
    else { py = blockIdx.z & 1; px = (blockIdx.z >> 1) & 1; co0 = (blockIdx.z >> 2) * 64; }

    // A tap offsets
    int ntaps, tAoff[9];
    if (LAST) {
        ntaps = 9;
        #pragma unroll
        for (int t = 0; t < 9; t++) tAoff[t] = ((t / 3) * 18 + (t % 3)) * 48;
    } else {
        ntaps = 0;
        for (int dy = (py ? 0 : -1); dy <= 1; dy++)
            for (int dx = (px ? 0 : -1); dx <= 1; dx++)
                tAoff[ntaps++] = ((dy + 1) * 18 + (dx + 1)) * 48;
    }
    const int nchunks = CIN >> 4;
    const int niter = nchunks * ntaps;          // even for all configs used
    const int zbase = (LAST ? 0 : blockIdx.z) * nchunks;

    const u32 smem_u = (u32)__cvta_generic_to_shared(smem);
    const u32 Abase = smem_u;
    const u32 Bbase = smem_u + 2 * ASTG;
    const u32 mbar_u = (u32)__cvta_generic_to_shared(mbarB);

    auto loadA = [&](int chunk, int slot) {
        const int ci0 = chunk << 4;
        #pragma unroll
        for (int k = 0; k < (NSITES * 2 + 255) / 256; k++) {
            int idx = tid + k * 256;
            if (idx < NSITES * 2) {
                int site = idx >> 1, seg = idx & 1;
                int r = site / 18, c = site % 18;
                int gy = y0 - 1 + r, gx = x0 - 1 + c;
                bool ok = (unsigned)gy < (unsigned)H && (unsigned)gx < (unsigned)W;
                const __half* src = ok ? (inA + ((size_t)(gy * W + gx) * CIN + ci0 + seg * 8)) : inA;
                u32 dst = Abase + slot * ASTG + site * 48 + seg * 16;
                CPASYNC(dst, src, ok ? 16 : 0);
            }
        }
    };
    auto issueB = [&](int tap, int chunk, int slot) {
        if (tid == 0) {
            u32 mb = mbar_u + slot * 8;
            MBAR_EXPECT_TX(mb, BSTG);
            const __half* src = Wt + ((size_t)(zbase + chunk) * 9 + tap) * (NTILE * 16);
            TMA_BULK(Bbase + slot * BSTG, src, BSTG, mb);
        }
    };

    // init + prologue: A(0) + B stages 0..3 (slots 0..3 of 6)
    if (tid == 0) {
        #pragma unroll
        for (int s = 0; s < 6; s++) MBAR_INIT(mbar_u + s * 8, 1);
    }
    loadA(0, 0); CPCOMMIT();
    __syncthreads();                           // init visible before TMA arrives
    int pf_tap = 0, pf_chunk = 0;
    for (int k = 0; k < 4; k++) {
        issueB(pf_tap, pf_chunk, k);
        if (++pf_tap == ntaps) { pf_tap = 0; pf_chunk++; }
    }

    float acc[MI][NI][4];
    #pragma unroll
    for (int mi = 0; mi < MI; mi++)
        #pragma unroll
        for (int ni = 0; ni < NI; ni++)
            #pragma unroll
            for (int k = 0; k < 4; k++) acc[mi][ni][k] = 0.f;

    const int la = lane & 7, ms = lane >> 3;
    const u32 aoff_lane = (u32)((la + ((ms & 1) << 3)) * 48 + ((ms >> 1) << 4));
    const int rb = la + ((lane >> 4) << 3);
    const u32 boff_lane = (u32)(rb * 32 + (((lane >> 3) & 1) << 4));

    auto compute = [&](int tap, int chunk, int slot) {
        const u32 Astage = Abase + (chunk & 1) * ASTG + tAoff[tap] + aoff_lane;
        const u32 Bstage = Bbase + slot * BSTG + warp_n * (NI * 8 * 32) + boff_lane;
        u32 a[MI][4], b[NPAIR][4];
        #pragma unroll
        for (int mi = 0; mi < MI; mi++) {
            int ylocal = warp_m * MI + mi;
            LDSM4(a[mi][0], a[mi][1], a[mi][2], a[mi][3], Astage + ylocal * (18 * 48));
        }
        #pragma unroll
        for (int p2 = 0; p2 < NPAIR; p2++)
            LDSM4(b[p2][0], b[p2][1], b[p2][2], b[p2][3], Bstage + p2 * (16 * 32));
        #pragma unroll
        for (int mi = 0; mi < MI; mi++)
            #pragma unroll
            for (int ni = 0; ni < NI; ni++)
                MMA16816(acc[mi][ni][0], acc[mi][ni][1], acc[mi][ni][2], acc[mi][ni][3],
                         a[mi][0], a[mi][1], a[mi][2], a[mi][3],
                         b[ni >> 1][(ni & 1) * 2], b[ni >> 1][(ni & 1) * 2 + 1]);
    };

    int cur_tap = 0, cur_chunk = 0;
    for (int i = 0; i < niter; i += 2) {
        int tap1 = cur_tap + 1, chunk1 = cur_chunk;
        if (tap1 == ntaps) { tap1 = 0; chunk1++; }

        // A residency for any chunk whose first tap is in this pair.
        // Placed BEFORE any new issues, so it never waits on same-pair loads.
        if (cur_tap == 0 || tap1 == 0) CPWAIT(0);

        const int s0 = i % 6, s1 = (i + 1) % 6;
        MBAR_WAIT(mbar_u + s0 * 8, (i / 6) & 1);
        MBAR_WAIT(mbar_u + s1 * 8, ((i + 1) / 6) & 1);
        __syncthreads();                       // slots (i+4)%6,(i+5)%6 fully consumed

        if (i + 4 < niter) {
            issueB(pf_tap, pf_chunk, (i + 4) % 6);
            if (++pf_tap == ntaps) { pf_tap = 0; pf_chunk++; }
        }
        if (i + 5 < niter) {
            issueB(pf_tap, pf_chunk, (i + 5) % 6);
            if (++pf_tap == ntaps) { pf_tap = 0; pf_chunk++; }
        }
        {
            int sc = (cur_tap == 0) ? cur_chunk : ((tap1 == 0) ? chunk1 : -1);
            if (sc >= 0 && sc + 1 < nchunks) { loadA(sc + 1, (sc + 1) & 1); CPCOMMIT(); }
        }

        compute(cur_tap, cur_chunk, s0);
        compute(tap1, chunk1, s1);

        cur_tap = tap1 + 1; cur_chunk = chunk1;
        if (cur_tap == ntaps) { cur_tap = 0; cur_chunk++; }
    }

    // -------- quant epilogue --------
    float addA, invA, clpv = 0.f, sclv = 0.f, addB = 0.f, invB = 0.f;
    if (!LAST) {
        addA = g_params[stage*6+0]; invA = g_params[stage*6+1];
        clpv = g_params[stage*6+2]; sclv = g_params[stage*6+3];
        addB = g_params[stage*6+4]; invB = g_params[stage*6+5];
    } else {
        addA = g_params[18]; invA = g_params[19];
    }
    const int W2 = 2 * W;

    if (!LAST) {
        __half* out = (__half*)outp;
        #pragma unroll
        for (int mi = 0; mi < MI; mi++) {
            int ylocal = warp_m * MI + mi;
            int oy = 2 * (y0 + ylocal) + py;
            #pragma unroll
            for (int ni = 0; ni < NI; ni++) {
                int co = co0 + warp_n * (NI * 8) + ni * 8 + (lane & 3) * 2;
                float b0f = bq[co], b1f = bq[co + 1];
                float m0f = mul[co], m1f = mul[co + 1];
                #pragma unroll
                for (int h = 0; h < 2; h++) {
                    int xl = (lane >> 2) + h * 8;
                    int ox = 2 * (x0 + xl) + px;
                    float v0 = acc[mi][ni][h * 2 + 0];
                    float v1 = acc[mi][ni][h * 2 + 1];
                    v0 = floorf(((v0 + b0f) * m0f + addA) * invA);
                    v0 = fminf(fmaxf(v0, 0.f), clpv);
                    v0 = floorf((v0 * sclv + addB) * invB);
                    v1 = floorf(((v1 + b1f) * m1f + addA) * invA);
                    v1 = fminf(fmaxf(v1, 0.f), clpv);
                    v1 = floorf((v1 * sclv + addB) * invB);
                    __half2 hv = __floats2half2_rn(v0, v1);
                    *(__half2*)(out + ((size_t)oy * W2 + ox) * COUT + co) = hv;
                }
            }
        }
    } else {
        float* out = (float*)outp;
        const int PLANE = W2 * 2 * H;
        #pragma unroll
        for (int mi = 0; mi < MI; mi++) {
            int ylocal = warp_m * MI + mi;
            #pragma unroll
            for (int ni = 0; ni < NI; ni++) {
                int nbase = ni * 8 + (lane & 3) * 2;
                #pragma unroll
                for (int h = 0; h < 2; h++) {
                    int xl = (lane >> 2) + h * 8;
                    #pragma unroll
                    for (int j = 0; j < 2; j++) {
                        int n = nbase + j;
                        int p = n >> 2, c = n & 3;
                        if (c < 3) {
                            int pyy = p >> 1, pxx = p & 1;
                            int oy = 2 * (y0 + ylocal) + pyy;
                            int ox = 2 * (x0 + xl) + pxx;
                            float v = acc[mi][ni][h * 2 + j];
                            v = (v + bq[c]) * mul[c];
                            v = floorf((v + addA) * invA);
                            out[(size_t)c * PLANE + (size_t)oy * W2 + ox] = v / 255.0f;
                        }
                    }
                }
            }
        }
    }
}

// ---------------- host launcher (graph-capturable: kernel launches only) -------
extern "C" void kernel_launch(void* const* d_in, const int* in_sizes, int n_in,
                              void* d_out, int out_size)
{
    const float* x     = (const float*)d_in[0];
    const float* w1    = (const float*)d_in[1];
    const float* b1    = (const float*)d_in[2];
    const float* w2    = (const float*)d_in[3];
    const float* b2    = (const float*)d_in[4];
    const float* w3    = (const float*)d_in[5];
    const float* b3    = (const float*)d_in[6];
    const float* w4    = (const float*)d_in[7];
    const float* b4    = (const float*)d_in[8];
    const float* m0    = (const float*)d_in[9];
    const float* m1    = (const float*)d_in[10];
    const float* m2    = (const float*)d_in[11];
    const float* m3    = (const float*)d_in[12];
    const float* relus = (const float*)d_in[13];
    const int*   dvds  = (const int*)d_in[14];
    const int*   bitsp = (n_in > 15) ? (const int*)d_in[15] : nullptr;

    __half *xh, *h0, *h1, *h2, *wb1, *wb2, *wb3, *wb4;
    float *b1q, *b2q, *b3q, *b4q;
    cudaGetSymbolAddress((void**)&xh,  g_xh);
    cudaGetSymbolAddress((void**)&h0,  g_h0);
    cudaGetSymbolAddress((void**)&h1,  g_h1);
    cudaGetSymbolAddress((void**)&h2,  g_h2);
    cudaGetSymbolAddress((void**)&wb1, g_wb1);
    cudaGetSymbolAddress((void**)&wb2, g_wb2);
    cudaGetSymbolAddress((void**)&wb3, g_wb3);
    cudaGetSymbolAddress((void**)&wb4, g_wb4);
    cudaGetSymbolAddress((void**)&b1q, g_b1q);
    cudaGetSymbolAddress((void**)&b2q, g_b2q);
    cudaGetSymbolAddress((void**)&b3q, g_b3q);
    cudaGetSymbolAddress((void**)&b4q, g_b4q);

    nchw2nhwc<<<(48*48*320 + 255)/256, 256>>>(x, xh, 320, 48*48);
    prep_wb3x<<<dim3(192, 3), 256>>>(w1, w2, w3);
    prep_wb4<<<(12*9*16 + 255)/256, 256>>>(w4);
    quant_scalars<<<1, 256>>>(b1, b2, b3, b4, relus, dvds, bitsp);

    // L1: 320ch 48x48 -> 192ch 96x96
    conv_mma<64,4,2,8,false><<<dim3(3, 6, 12), 256>>>(xh, h0, wb1, b1q, m0, 320, 192, 48, 48, 0);
    // L2: 192ch 96x96 -> 192ch 192x192
    conv_mma<64,4,2,16,false><<<dim3(6, 6, 12), 256>>>(h0, h1, wb2, b2q, m1, 192, 192, 96, 96, 1);
    // L3: 192ch 192x192 -> 192ch 384x384
    conv_mma<64,4,2,16,false><<<dim3(12, 12, 12), 256>>>(h1, h2, wb3, b3q, m2, 192, 192, 192, 192, 2);
    // L4: 192ch 384x384 -> 3ch 768x768, parity-folded N=16, f32 NCHW out
    conv_mma<16,8,1,16,true><<<dim3(24, 24, 1), 256>>>(h2, d_out, wb4, b4q, m3, 192, 3, 384, 384, 3);
}